// round 7
// baseline (speedup 1.0000x reference)
#include <cuda_runtime.h>
#include <cstddef>

// Shapes (fixed by the problem)
//  x_f:    (128, 256, 31, 31) f32
//  z_f:    (128, 256, 7, 7)   f32
//  heat_w: (1, 256, 3, 3), heat_b: (1,)
//  reg_w:  (4, 256, 3, 3), reg_b:  (4,)
//  out = concat(pred_heat (128,1,23,23), pred_reg (128,4,23,23)) f32

#define NB 128
#define NC 256
#define HEAT_ELEMS (NB * 529)          // 67712
#define OUT_ELEMS  (NB * 5 * 529)      // 338560

typedef unsigned long long ull;

// Packed f32x2 FMA (two independent exact fp32 FMAs in one instruction).
__device__ __forceinline__ ull fma2(ull a, ull b, ull c) {
    ull d;
    asm("fma.rn.f32x2 %0, %1, %2, %3;" : "=l"(d) : "l"(a), "l"(b), "l"(c));
    return d;
}

// smem layout, all channel-PAIR-packed float2:
//  sx2: 4 pairs x 31 rows x 34 f2   (stride 34 f2 -> conflict-free Phase B)
//  sz2: 4 x 49 f2
//  sc2: 4 x 25 x 26 f2              (even stride -> 16B-aligned LDS.128)
//  sw2: 4 pairs x 5 o x 9 taps f2
#define SX_F   (4 * 31 * 34 * 2)       // 8432 floats
#define SZ_F   (4 * 49 * 2)            // 392
#define SC_F   (4 * 25 * 26 * 2)       // 5200
#define SW_F   (4 * 5 * 9 * 2)         // 360
#define SMEM_FLOATS (SX_F + SZ_F + SC_F + SW_F)   // 14384 -> 57536 B (4 CTAs/SM)

// ---------------------------------------------------------------------------
// K0: write biases into out (out is poisoned to 0xAA by the harness).
// ---------------------------------------------------------------------------
__global__ void init_out_kernel(const float* __restrict__ heat_b,
                                const float* __restrict__ reg_b,
                                float* __restrict__ out)
{
    int i = blockIdx.x * 256 + threadIdx.x;
    if (i >= OUT_ELEMS) return;
    if (i < HEAT_ELEMS) {
        out[i] = heat_b[0];
    } else {
        int j = i - HEAT_ELEMS;
        int o = (j / 529) & 3;
        out[i] = reg_b[o];
    }
}

// ---------------------------------------------------------------------------
// K1 (fused): depthwise xcorr + both 3x3 head convs, channel-pair f32x2.
// Grid: 128*32 CTAs; CTA = (n, block of 8 channels). 256 threads, occ 4.
// Phase B: 13-slot ring buffer keeps live regs ~60 (fits 64-reg cap).
// Phase C: unit = (o, 8-pixel strip): weights amortized 8x, rows via LDS.128.
// ---------------------------------------------------------------------------
__global__ __launch_bounds__(256, 4)
void fused_kernel(const float* __restrict__ x_f, const float* __restrict__ z_f,
                  const float* __restrict__ heat_w, const float* __restrict__ reg_w,
                  float* __restrict__ out)
{
    extern __shared__ __align__(16) float sm[];
    float* sxf = sm;
    float* szf = sxf + SX_F;
    float* scf = szf + SZ_F;
    float* swf = scf + SC_F;

    ull* sx2 = reinterpret_cast<ull*>(sxf);
    ull* sz2 = reinterpret_cast<ull*>(szf);
    ull* sc2 = reinterpret_cast<ull*>(scf);
    ull* sw2 = reinterpret_cast<ull*>(swf);

    const int b   = blockIdx.x;
    const int n   = b >> 5;
    const int c0  = (b & 31) * 8;
    const int tid = threadIdx.x;

    // --- Phase A: staging into pair-interleaved layouts ---
    const float* xg = x_f + ((size_t)n * NC + c0) * 961;
    for (int i = tid; i < 8 * 961; i += 256) {
        int ch = i / 961;
        int q  = i - ch * 961;
        int r  = q / 31;
        int c  = q - r * 31;
        sxf[(((ch >> 1) * (31 * 34)) + r * 34 + c) * 2 + (ch & 1)] = xg[i];
    }
    const float* zg = z_f + ((size_t)n * NC + c0) * 49;
    for (int i = tid; i < 8 * 49; i += 256) {
        int ch = i / 49;
        int t  = i - ch * 49;
        szf[((ch >> 1) * 49 + t) * 2 + (ch & 1)] = zg[i];
    }
    for (int i = tid; i < 360; i += 256) {          // (ch, o, tap)
        int ch  = i / 45;
        int rr  = i - ch * 45;
        int o   = rr / 9;
        int tap = rr - o * 9;
        float v = (o == 0) ? heat_w[(c0 + ch) * 9 + tap]
                           : reg_w[(((o - 1) * NC) + c0 + ch) * 9 + tap];
        swf[((((ch >> 1) * 5) + o) * 9 + tap) * 2 + (ch & 1)] = v;
    }
    __syncthreads();

    // --- Phase B: depthwise xcorr, 13-col half-row of a channel PAIR ---
    if (tid < 200) {
        const int p    = tid / 50;           // channel pair 0..3
        const int rem  = tid - p * 50;
        const int y    = rem >> 1;           // corr row 0..24
        const int half = rem & 1;
        const int x0   = half ? 13 : 0;      // cols x0..x0+12 (13th dropped h1)

        ull acc[13];
        #pragma unroll
        for (int j = 0; j < 13; j++) acc[j] = 0ull;

        const ull* xb = sx2 + p * (31 * 34) + x0;
        const ull* zb = sz2 + p * 49;

        #pragma unroll
        for (int u = 0; u < 7; u++) {
            const ull* xrow = xb + (y + u) * 34;
            ull xw[13];                        // ring buffer, static indexing
            #pragma unroll
            for (int s = 0; s < 13; s++) xw[s] = xrow[s];
            #pragma unroll
            for (int v = 0; v < 7; v++) {
                if (v > 0) xw[(v + 12) % 13] = xrow[v + 12];
                const ull zv = zb[u * 7 + v];
                #pragma unroll
                for (int j = 0; j < 13; j++)
                    acc[j] = fma2(zv, xw[(v + j) % 13], acc[j]);
            }
        }

        ull* crow = sc2 + p * 650 + y * 26 + x0;
        #pragma unroll
        for (int j = 0; j < 13; j++)
            if (x0 + j <= 24) crow[j] = acc[j];   // half1 drops j==12
    }
    __syncthreads();

    // --- Phase C: unit = (output channel o, 8-pixel row strip) ---
    // 5 o x 23 rows x 3 strips (x0 = 0/8/16; last strip 7 valid px) = 345.
    float* outh = out + (size_t)n * 529;
    float* outr = out + HEAT_ELEMS + (size_t)n * 4 * 529;

    for (int uid = tid; uid < 345; uid += 256) {
        const int o  = uid / 69;
        const int r  = uid - o * 69;
        const int y  = r / 3;
        const int s  = r - y * 3;
        const int x0 = s * 8;

        ull acc[8];
        #pragma unroll
        for (int j = 0; j < 8; j++) acc[j] = 0ull;

        #pragma unroll
        for (int p = 0; p < 4; p++) {
            const ull* wp = sw2 + ((p * 5) + o) * 9;       // broadcast loads
            const ull* cb = sc2 + p * 650 + y * 26 + x0;   // 16B-aligned
            #pragma unroll
            for (int dy = 0; dy < 3; dy++) {
                ull row[10];                                // 5 x LDS.128
                #pragma unroll
                for (int k = 0; k < 5; k++) {
                    ulonglong2 t =
                        *reinterpret_cast<const ulonglong2*>(cb + dy * 26 + 2 * k);
                    row[2 * k] = t.x; row[2 * k + 1] = t.y;
                }
                const ull w0 = wp[dy * 3 + 0];
                const ull w1 = wp[dy * 3 + 1];
                const ull w2 = wp[dy * 3 + 2];
                #pragma unroll
                for (int j = 0; j < 8; j++) {
                    acc[j] = fma2(w0, row[j],     acc[j]);
                    acc[j] = fma2(w1, row[j + 1], acc[j]);
                    acc[j] = fma2(w2, row[j + 2], acc[j]);
                }
            }
        }
        // Note: last strip reads pad col 25 (garbage) into acc[7] only; acc[7]
        // is not stored for s==2, and garbage cannot corrupt other lanes/accs.

        float* dst = (o == 0) ? outh : (outr + (o - 1) * 529);
        const int wlim = (s == 2) ? 7 : 8;
        const int base = y * 23 + x0;
        #pragma unroll
        for (int j = 0; j < 8; j++)
            if (j < wlim) {
                float2 f = *reinterpret_cast<float2*>(&acc[j]);
                atomicAdd(&dst[base + j], f.x + f.y);
            }
    }
}

// ---------------------------------------------------------------------------
extern "C" void kernel_launch(void* const* d_in, const int* in_sizes, int n_in,
                              void* d_out, int out_size)
{
    const float *x_f = nullptr, *z_f = nullptr, *heat_w = nullptr,
                *heat_b = nullptr, *reg_w = nullptr, *reg_b = nullptr;
    for (int i = 0; i < n_in; i++) {
        switch (in_sizes[i]) {
            case 128 * 256 * 31 * 31: x_f    = (const float*)d_in[i]; break;
            case 128 * 256 * 7 * 7:   z_f    = (const float*)d_in[i]; break;
            case 1 * 256 * 3 * 3:     heat_w = (const float*)d_in[i]; break;
            case 1:                   heat_b = (const float*)d_in[i]; break;
            case 4 * 256 * 3 * 3:     reg_w  = (const float*)d_in[i]; break;
            case 4:                   reg_b  = (const float*)d_in[i]; break;
            default: break;
        }
    }
    float* out = (float*)d_out;

    const int smem1 = SMEM_FLOATS * (int)sizeof(float);   // 57536 B
    cudaFuncSetAttribute(fused_kernel,
                         cudaFuncAttributeMaxDynamicSharedMemorySize, smem1);

    init_out_kernel<<<(OUT_ELEMS + 255) / 256, 256>>>(heat_b, reg_b, out);
    fused_kernel<<<NB * 32, 256, smem1>>>(x_f, z_f, heat_w, reg_w, out);
}